// round 1
// baseline (speedup 1.0000x reference)
#include <cuda_runtime.h>
#include <math.h>

#define NSEQ 2048
#define BATCH 2
#define DIM 1024
#define NHEAD 16
#define HDIM 64
#define MROWS 4096          // BATCH*NSEQ
#define WINR 128
#define MEMM 256
#define ASCALE 0.125f       // HD^-0.5

// ---------------- scratch (device globals; no allocation allowed) ----------
__device__ float g_t[3 * MROWS * 64];                    // x@U * alpha
__device__ float g_l[3 * MROWS * 4];                     // x@A
__device__ float g_qkv[3 * BATCH * NHEAD * NSEQ * HDIM]; // q,k,v in [B,H,N,HD]
__device__ float g_comb[BATCH * NHEAD * NSEQ * HDIM];    // local+glob+rag

// ---------------------------------------------------------------------------
// t = x @ U, scaled by alpha per column.  M=4096, K=1024, N=64.
// tile 64x64, Kc=64, 256 threads, 4x4 micro, K-major smem.
// ---------------------------------------------------------------------------
__global__ __launch_bounds__(256) void k_xu(const float* __restrict__ X,
                                            const float* __restrict__ U,
                                            const float* __restrict__ alpha,
                                            float* __restrict__ T) {
    __shared__ float a_s[64][68];
    __shared__ float b_s[64][68];
    int t = threadIdx.x;
    int m0 = blockIdx.x * 64;
    int tq = t & 15, tn = t >> 4;
    float acc[4][4] = {};
    for (int k0 = 0; k0 < 1024; k0 += 64) {
#pragma unroll
        for (int rep = 0; rep < 4; rep++) {
            int fidx = t + rep * 256;        // over 1024 float4s (64m x 16kq)
            int m = fidx >> 4;
            int kq = fidx & 15;
            float4 v = *(const float4*)&X[(size_t)(m0 + m) * 1024 + k0 + kq * 4];
            a_s[kq * 4 + 0][m] = v.x; a_s[kq * 4 + 1][m] = v.y;
            a_s[kq * 4 + 2][m] = v.z; a_s[kq * 4 + 3][m] = v.w;
        }
#pragma unroll
        for (int rep = 0; rep < 4; rep++) {
            int fidx = t + rep * 256;        // 64kk x 16nq
            int kk = fidx >> 4;
            int nq = fidx & 15;
            float4 v = *(const float4*)&U[(size_t)(k0 + kk) * 64 + nq * 4];
            *(float4*)&b_s[kk][nq * 4] = v;
        }
        __syncthreads();
#pragma unroll
        for (int kk = 0; kk < 64; kk++) {
            float4 av = *(const float4*)&a_s[kk][tq * 4];
            float4 bv = *(const float4*)&b_s[kk][tn * 4];
            float aa[4] = {av.x, av.y, av.z, av.w};
            float bb[4] = {bv.x, bv.y, bv.z, bv.w};
#pragma unroll
            for (int i = 0; i < 4; i++)
#pragma unroll
                for (int j = 0; j < 4; j++) acc[i][j] += aa[i] * bb[j];
        }
        __syncthreads();
    }
#pragma unroll
    for (int i = 0; i < 4; i++) {
        float4 o;
        o.x = acc[i][0] * alpha[tn * 4 + 0];
        o.y = acc[i][1] * alpha[tn * 4 + 1];
        o.z = acc[i][2] * alpha[tn * 4 + 2];
        o.w = acc[i][3] * alpha[tn * 4 + 3];
        *(float4*)&T[(size_t)(m0 + tq * 4 + i) * 64 + tn * 4] = o;
    }
}

// ---------------------------------------------------------------------------
// l = x @ A   (M=4096, K=1024, N=4).  one block per row.
// ---------------------------------------------------------------------------
__global__ __launch_bounds__(128) void k_lora(const float* __restrict__ X,
                                              const float* __restrict__ A,
                                              float* __restrict__ L) {
    int m = blockIdx.x;
    int t = threadIdx.x;
    float p[4] = {};
    for (int k = t; k < 1024; k += 128) {
        float xv = X[(size_t)m * 1024 + k];
#pragma unroll
        for (int j = 0; j < 4; j++) p[j] += xv * A[k * 4 + j];
    }
    __shared__ float red[4][128];
#pragma unroll
    for (int j = 0; j < 4; j++) red[j][t] = p[j];
    __syncthreads();
    for (int s = 64; s > 0; s >>= 1) {
        if (t < s) {
#pragma unroll
            for (int j = 0; j < 4; j++) red[j][t] += red[j][t + s];
        }
        __syncthreads();
    }
    if (t < 4) L[(size_t)m * 4 + t] = red[t][0];
}

// ---------------------------------------------------------------------------
// proj: out = [t | l] @ [V^T ; Blora] + bias, scattered to [B,H,N,HD].
// M=4096, N=1024, K=68. tile 64x64. grid (64, 16); h = blockIdx.y.
// ---------------------------------------------------------------------------
__global__ __launch_bounds__(256) void k_proj(const float* __restrict__ T,
                                              const float* __restrict__ L,
                                              const float* __restrict__ V,
                                              const float* __restrict__ Blora,
                                              const float* __restrict__ bias,
                                              float* __restrict__ O) {
    __shared__ float a_s[68][68];
    __shared__ float b_s[68][68];
    int t = threadIdx.x;
    int m0 = blockIdx.x * 64;
    int n0 = blockIdx.y * 64;
    int tq = t & 15, tn = t >> 4;

#pragma unroll
    for (int rep = 0; rep < 4; rep++) {           // T transpose-load 64x64
        int fidx = t + rep * 256;
        int m = fidx >> 4, kq = fidx & 15;
        float4 v = *(const float4*)&T[(size_t)(m0 + m) * 64 + kq * 4];
        a_s[kq * 4 + 0][m] = v.x; a_s[kq * 4 + 1][m] = v.y;
        a_s[kq * 4 + 2][m] = v.z; a_s[kq * 4 + 3][m] = v.w;
    }
    if (t < 64) {                                 // lora rows 64..67
        float4 lv = *(const float4*)&L[(size_t)(m0 + t) * 4];
        a_s[64][t] = lv.x; a_s[65][t] = lv.y; a_s[66][t] = lv.z; a_s[67][t] = lv.w;
    }
#pragma unroll
    for (int rep = 0; rep < 4; rep++) {           // V transpose-load (V is [1024,64])
        int fidx = t + rep * 256;
        int n = fidx >> 4, kq = fidx & 15;
        float4 v = *(const float4*)&V[(size_t)(n0 + n) * 64 + kq * 4];
        b_s[kq * 4 + 0][n] = v.x; b_s[kq * 4 + 1][n] = v.y;
        b_s[kq * 4 + 2][n] = v.z; b_s[kq * 4 + 3][n] = v.w;
    }
    {                                             // Blora rows 64..67
        int j = t >> 6, n = t & 63;
        b_s[64 + j][n] = Blora[(size_t)j * 1024 + n0 + n];
    }
    __syncthreads();

    float acc[4][4] = {};
#pragma unroll
    for (int kk = 0; kk < 68; kk++) {
        float4 av = *(const float4*)&a_s[kk][tq * 4];
        float4 bv = *(const float4*)&b_s[kk][tn * 4];
        float aa[4] = {av.x, av.y, av.z, av.w};
        float bb[4] = {bv.x, bv.y, bv.z, bv.w};
#pragma unroll
        for (int i = 0; i < 4; i++)
#pragma unroll
            for (int j = 0; j < 4; j++) acc[i][j] += aa[i] * bb[j];
    }

    int h = blockIdx.y;                           // n0 = h*64
#pragma unroll
    for (int i = 0; i < 4; i++) {
        int m = m0 + tq * 4 + i;
        int bi = m >> 11, ni = m & 2047;
        float4 o;
        o.x = acc[i][0] + bias[n0 + tn * 4 + 0];
        o.y = acc[i][1] + bias[n0 + tn * 4 + 1];
        o.z = acc[i][2] + bias[n0 + tn * 4 + 2];
        o.w = acc[i][3] + bias[n0 + tn * 4 + 3];
        *(float4*)&O[((size_t)(bi * 16 + h) * 2048 + ni) * 64 + tn * 4] = o;
    }
}

// ---------------------------------------------------------------------------
// flash attention, one kernel, 3 branches. BR: 0=local(win 128), 1=glob(32
// strided keys), 2=rag(256 memory keys). 64q x 64k tiles, online softmax.
// ---------------------------------------------------------------------------
template <int BR>
__global__ __launch_bounds__(256) void k_attn(const float* __restrict__ Q,
                                              const float* __restrict__ K,
                                              const float* __restrict__ V,
                                              float* __restrict__ O) {
    extern __shared__ float sm[];
    float* q_s = sm;                 // [hd][q]   64x68
    float* k_s = sm + 64 * 68;       // [hd][key] 64x68
    float* v_s = sm + 2 * 64 * 68;   // [key][hd] 64x68
    float* p_s = sm + 3 * 64 * 68;   // [key][q]  64x68
    __shared__ float mrow[64], lrow[64], fac[64];

    int t = threadIdx.x;
    int qt = blockIdx.x;   // 0..31
    int h = blockIdx.y;
    int b = blockIdx.z;
    int tq = t & 15, tz = t >> 4;
    size_t qbase = ((size_t)(b * 16 + h) * 2048 + qt * 64) * 64;

#pragma unroll
    for (int rep = 0; rep < 4; rep++) {           // load q (transpose to hd-major)
        int fidx = t + rep * 256;
        int q = fidx >> 4, hq = fidx & 15;
        float4 v = *(const float4*)&Q[qbase + (size_t)q * 64 + hq * 4];
        q_s[(hq * 4 + 0) * 68 + q] = v.x; q_s[(hq * 4 + 1) * 68 + q] = v.y;
        q_s[(hq * 4 + 2) * 68 + q] = v.z; q_s[(hq * 4 + 3) * 68 + q] = v.w;
    }
    if (t < 64) { mrow[t] = -1e30f; lrow[t] = 0.f; }
    float acc[4][4] = {};
    __syncthreads();

    const int NC = (BR == 0) ? 5 : (BR == 1) ? 1 : 4;
    for (int c = 0; c < NC; c++) {
#pragma unroll
        for (int rep = 0; rep < 4; rep++) {       // load K (hd-major) + V (key-major)
            int fidx = t + rep * 256;
            int kk = fidx >> 4, hq = fidx & 15;
            size_t rowoff = 0; bool valid;
            if (BR == 0) {
                int gk = qt * 64 - 128 + c * 64 + kk;
                valid = (gk >= 0 && gk < 2048);
                rowoff = ((size_t)(b * 16 + h) * 2048 + (gk < 0 ? 0 : gk)) * 64;
            } else if (BR == 1) {
                valid = kk < 32;
                rowoff = ((size_t)(b * 16 + h) * 2048 + (valid ? kk * 64 : 0)) * 64;
            } else {
                valid = true;
                rowoff = ((size_t)b * 256 + c * 64 + kk) * 64;
            }
            float4 kv = valid ? *(const float4*)&K[rowoff + hq * 4] : make_float4(0, 0, 0, 0);
            float4 vv = valid ? *(const float4*)&V[rowoff + hq * 4] : make_float4(0, 0, 0, 0);
            k_s[(hq * 4 + 0) * 68 + kk] = kv.x; k_s[(hq * 4 + 1) * 68 + kk] = kv.y;
            k_s[(hq * 4 + 2) * 68 + kk] = kv.z; k_s[(hq * 4 + 3) * 68 + kk] = kv.w;
            *(float4*)&v_s[kk * 68 + hq * 4] = vv;
        }
        __syncthreads();

        float sc[4][4] = {};
#pragma unroll
        for (int hd = 0; hd < 64; hd++) {
            float4 qv = *(const float4*)&q_s[hd * 68 + tq * 4];
            float4 kv = *(const float4*)&k_s[hd * 68 + tz * 4];
            float aa[4] = {qv.x, qv.y, qv.z, qv.w};
            float bb[4] = {kv.x, kv.y, kv.z, kv.w};
#pragma unroll
            for (int i = 0; i < 4; i++)
#pragma unroll
                for (int j = 0; j < 4; j++) sc[i][j] += aa[i] * bb[j];
        }
#pragma unroll
        for (int j = 0; j < 4; j++) {
            int kl = tz * 4 + j;
#pragma unroll
            for (int i = 0; i < 4; i++) {
                int gq = qt * 64 + tq * 4 + i;
                bool ok;
                if (BR == 0) {
                    int gk = qt * 64 - 128 + c * 64 + kl;
                    int dd = gq - gk; if (dd < 0) dd = -dd;
                    ok = (gk >= 0) && (gk < 2048) && (dd <= WINR);
                } else if (BR == 1) ok = kl < 32;
                else ok = true;
                p_s[kl * 68 + tq * 4 + i] = ok ? sc[i][j] * ASCALE : -1e30f;
            }
        }
        __syncthreads();

        if (t < 64) {                              // online softmax row pass
            int q = t;
            float om = mrow[q];
            float mx = om;
            for (int kk = 0; kk < 64; kk++) mx = fmaxf(mx, p_s[kk * 68 + q]);
            float okf = (mx > -1e29f) ? 1.f : 0.f;
            float sum = 0.f;
            for (int kk = 0; kk < 64; kk++) {
                float e = okf * __expf(p_s[kk * 68 + q] - mx);
                p_s[kk * 68 + q] = e;
                sum += e;
            }
            float f = __expf(om - mx);
            lrow[q] = lrow[q] * f + sum;
            mrow[q] = mx;
            fac[q] = f;
        }
        __syncthreads();

        float fi[4];
#pragma unroll
        for (int i = 0; i < 4; i++) fi[i] = fac[tq * 4 + i];
#pragma unroll
        for (int i = 0; i < 4; i++)
#pragma unroll
            for (int j = 0; j < 4; j++) acc[i][j] *= fi[i];
#pragma unroll
        for (int kk = 0; kk < 64; kk++) {
            float4 pv = *(const float4*)&p_s[kk * 68 + tq * 4];
            float4 vv = *(const float4*)&v_s[kk * 68 + tz * 4];
            float aa[4] = {pv.x, pv.y, pv.z, pv.w};
            float bb[4] = {vv.x, vv.y, vv.z, vv.w};
#pragma unroll
            for (int i = 0; i < 4; i++)
#pragma unroll
                for (int j = 0; j < 4; j++) acc[i][j] += aa[i] * bb[j];
        }
        __syncthreads();
    }

    float li[4];
#pragma unroll
    for (int i = 0; i < 4; i++) li[i] = 1.f / lrow[tq * 4 + i];
#pragma unroll
    for (int i = 0; i < 4; i++)
#pragma unroll
        for (int j = 0; j < 4; j++)
            q_s[(tq * 4 + i) * 68 + tz * 4 + j] = acc[i][j] * li[i];
    __syncthreads();
#pragma unroll
    for (int rep = 0; rep < 4; rep++) {
        int fidx = t + rep * 256;
        int q = fidx >> 4, hq = fidx & 15;
        float4 o;
        o.x = q_s[q * 68 + hq * 4 + 0]; o.y = q_s[q * 68 + hq * 4 + 1];
        o.z = q_s[q * 68 + hq * 4 + 2]; o.w = q_s[q * 68 + hq * 4 + 3];
        if (BR != 0) {
            float4 prev = *(const float4*)&O[qbase + (size_t)q * 64 + hq * 4];
            o.x += prev.x; o.y += prev.y; o.z += prev.z; o.w += prev.w;
        }
        *(float4*)&O[qbase + (size_t)q * 64 + hq * 4] = o;
    }
}

// ---------------------------------------------------------------------------
// out = fused @ out_W^T + out_b.  M=4096, N=1024, K=1024.
// tile 128x128, Kc=16, 8x8 micro (FMA bound). fused gathered from g_comb.
// ---------------------------------------------------------------------------
__global__ __launch_bounds__(256) void k_outproj(const float* __restrict__ C,
                                                 const float* __restrict__ W,
                                                 const float* __restrict__ bias,
                                                 float* __restrict__ out) {
    __shared__ float a_s[16][132];
    __shared__ float b_s[16][132];
    int t = threadIdx.x;
    int m0 = blockIdx.x * 128, n0 = blockIdx.y * 128;
    int tq = t & 15, tn = t >> 4;
    float acc[8][8] = {};
    for (int k0 = 0; k0 < 1024; k0 += 16) {
        int hblk = k0 >> 6;
#pragma unroll
        for (int rep = 0; rep < 2; rep++) {       // fused gather -> K-major
            int fidx = t + rep * 256;             // 512 float4s: 128m x 4kq
            int m = fidx >> 2, kq = fidx & 3;
            int mg = m0 + m;
            int bi = mg >> 11, ni = mg & 2047;
            int kg = k0 + kq * 4;
            float4 v = *(const float4*)&C[((size_t)(bi * 16 + hblk) * 2048 + ni) * 64 + (kg & 63)];
            a_s[kq * 4 + 0][m] = v.x; a_s[kq * 4 + 1][m] = v.y;
            a_s[kq * 4 + 2][m] = v.z; a_s[kq * 4 + 3][m] = v.w;
        }
#pragma unroll
        for (int rep = 0; rep < 2; rep++) {       // W[n][k] -> K-major
            int fidx = t + rep * 256;
            int n = fidx >> 2, kq = fidx & 3;
            float4 v = *(const float4*)&W[(size_t)(n0 + n) * 1024 + k0 + kq * 4];
            b_s[kq * 4 + 0][n] = v.x; b_s[kq * 4 + 1][n] = v.y;
            b_s[kq * 4 + 2][n] = v.z; b_s[kq * 4 + 3][n] = v.w;
        }
        __syncthreads();
#pragma unroll
        for (int kk = 0; kk < 16; kk++) {
            float4 a0 = *(const float4*)&a_s[kk][tq * 8];
            float4 a1 = *(const float4*)&a_s[kk][tq * 8 + 4];
            float4 b0 = *(const float4*)&b_s[kk][tn * 8];
            float4 b1 = *(const float4*)&b_s[kk][tn * 8 + 4];
            float aa[8] = {a0.x, a0.y, a0.z, a0.w, a1.x, a1.y, a1.z, a1.w};
            float bb[8] = {b0.x, b0.y, b0.z, b0.w, b1.x, b1.y, b1.z, b1.w};
#pragma unroll
            for (int i = 0; i < 8; i++)
#pragma unroll
                for (int j = 0; j < 8; j++) acc[i][j] += aa[i] * bb[j];
        }
        __syncthreads();
    }
#pragma unroll
    for (int i = 0; i < 8; i++) {
        int m = m0 + tq * 8 + i;
#pragma unroll
        for (int jq = 0; jq < 2; jq++) {
            float4 o;
            o.x = acc[i][jq * 4 + 0] + bias[n0 + tn * 8 + jq * 4 + 0];
            o.y = acc[i][jq * 4 + 1] + bias[n0 + tn * 8 + jq * 4 + 1];
            o.z = acc[i][jq * 4 + 2] + bias[n0 + tn * 8 + jq * 4 + 2];
            o.w = acc[i][jq * 4 + 3] + bias[n0 + tn * 8 + jq * 4 + 3];
            *(float4*)&out[(size_t)m * 1024 + n0 + tn * 8 + jq * 4] = o;
        }
    }
}

// ---------------------------------------------------------------------------
// temporal / identity / citation heads from combined[:, h=0].
// ---------------------------------------------------------------------------
__global__ __launch_bounds__(128) void k_heads(const float* __restrict__ C,
                                               const float* __restrict__ tW, const float* __restrict__ tb,
                                               const float* __restrict__ iW, const float* __restrict__ ib,
                                               const float* __restrict__ cW, const float* __restrict__ cb,
                                               float* __restrict__ out) {
    int r = blockIdx.x;              // b*2048 + n
    int b = r >> 11, n = r & 2047;
    __shared__ float last[64];
    int t = threadIdx.x;
    if (t < 64) last[t] = C[((size_t)(b * 16) * 2048 + n) * 64 + t];
    __syncthreads();
    if (t < 2) {
        float s = tb[t];
        for (int k = 0; k < 64; k++) s += last[k] * tW[t * 64 + k];
        out[4194304 + (size_t)r * 2 + t] = s;
    } else if (t < 66) {
        int j = t - 2;
        float s = ib[j];
        for (int k = 0; k < 64; k++) s += last[k] * iW[j * 64 + k];
        out[4202496 + (size_t)r * 64 + j] = s;
    } else if (t < 98) {
        int j = t - 66;
        float s = cb[j];
        for (int k = 0; k < 64; k++) s += last[k] * cW[j * 64 + k];
        out[4464640 + (size_t)r * 32 + j] = s;
    }
}

// ---------------------------------------------------------------------------
extern "C" void kernel_launch(void* const* d_in, const int* in_sizes, int n_in,
                              void* d_out, int out_size) {
    const float* x   = (const float*)d_in[0];
    const float* mem = (const float*)d_in[1];
    const float* U[3]  = {(const float*)d_in[2],  (const float*)d_in[8],  (const float*)d_in[14]};
    const float* Vw[3] = {(const float*)d_in[3],  (const float*)d_in[9],  (const float*)d_in[15]};
    const float* al[3] = {(const float*)d_in[4],  (const float*)d_in[10], (const float*)d_in[16]};
    const float* A[3]  = {(const float*)d_in[5],  (const float*)d_in[11], (const float*)d_in[17]};
    const float* Bl[3] = {(const float*)d_in[6],  (const float*)d_in[12], (const float*)d_in[18]};
    const float* bi[3] = {(const float*)d_in[7],  (const float*)d_in[13], (const float*)d_in[19]};
    const float* outW = (const float*)d_in[20];
    const float* outb = (const float*)d_in[21];
    const float* tW = (const float*)d_in[22];
    const float* tb = (const float*)d_in[23];
    const float* iW = (const float*)d_in[24];
    const float* ib = (const float*)d_in[25];
    const float* cW = (const float*)d_in[26];
    const float* cb = (const float*)d_in[27];
    float* out = (float*)d_out;

    void *pT, *pL, *pQKV, *pC;
    cudaGetSymbolAddress(&pT, g_t);
    cudaGetSymbolAddress(&pL, g_l);
    cudaGetSymbolAddress(&pQKV, g_qkv);
    cudaGetSymbolAddress(&pC, g_comb);
    float* Tb = (float*)pT;
    float* Lb = (float*)pL;
    float* QKV = (float*)pQKV;
    float* Cb = (float*)pC;
    const size_t QSZ = (size_t)BATCH * NHEAD * NSEQ * HDIM;

    for (int p = 0; p < 3; p++) {
        k_xu<<<64, 256>>>(x, U[p], al[p], Tb + (size_t)p * MROWS * 64);
        k_lora<<<4096, 128>>>(x, A[p], Lb + (size_t)p * MROWS * 4);
        k_proj<<<dim3(64, 16), 256>>>(Tb + (size_t)p * MROWS * 64,
                                      Lb + (size_t)p * MROWS * 4,
                                      Vw[p], Bl[p], bi[p], QKV + p * QSZ);
    }

    const int SMEM_ATTN = 4 * 64 * 68 * 4;  // 69632 B
    cudaFuncSetAttribute(k_attn<0>, cudaFuncAttributeMaxDynamicSharedMemorySize, SMEM_ATTN);
    cudaFuncSetAttribute(k_attn<1>, cudaFuncAttributeMaxDynamicSharedMemorySize, SMEM_ATTN);
    cudaFuncSetAttribute(k_attn<2>, cudaFuncAttributeMaxDynamicSharedMemorySize, SMEM_ATTN);
    dim3 ag(32, 16, 2);
    k_attn<0><<<ag, 256, SMEM_ATTN>>>(QKV, QKV + QSZ, QKV + 2 * QSZ, Cb);
    k_attn<1><<<ag, 256, SMEM_ATTN>>>(QKV, QKV + QSZ, QKV + 2 * QSZ, Cb);
    k_attn<2><<<ag, 256, SMEM_ATTN>>>(QKV, mem, mem, Cb);

    k_outproj<<<dim3(32, 8), 256>>>(Cb, outW, outb, out);
    k_heads<<<4096, 128>>>(Cb, tW, tb, iW, ib, cW, cb, out);
}

// round 2
// speedup vs baseline: 1.1232x; 1.1232x over previous
#include <cuda_runtime.h>
#include <math.h>

#define NSEQ 2048
#define BATCH 2
#define DIM 1024
#define NHEAD 16
#define HDIM 64
#define MROWS 4096
#define WINR 128
#define ASCALE 0.125f

typedef unsigned long long u64;
struct P3 { const float* a; const float* b; const float* c; };
__device__ __forceinline__ const float* sel(P3 p, int i) {
    return i == 0 ? p.a : (i == 1 ? p.b : p.c);
}

__device__ __forceinline__ u64 PK2(float lo, float hi) {
    u64 r; asm("mov.b64 %0,{%1,%2};" : "=l"(r) : "f"(lo), "f"(hi)); return r;
}
__device__ __forceinline__ u64 DUP(float v) { return PK2(v, v); }
__device__ __forceinline__ void FMA2(u64& d, u64 a, u64 b) {
    asm("fma.rn.f32x2 %0,%1,%2,%0;" : "+l"(d) : "l"(a), "l"(b));
}
__device__ __forceinline__ void MUL2(u64& d, u64 a) {
    asm("mul.rn.f32x2 %0,%0,%1;" : "+l"(d) : "l"(a));
}
__device__ __forceinline__ float2 UPK(u64 v) {
    float2 f; asm("mov.b64 {%0,%1},%2;" : "=f"(f.x), "=f"(f.y) : "l"(v)); return f;
}

// ---------------- scratch ----------------
__device__ float g_t[3 * MROWS * 64];
__device__ float g_l[3 * MROWS * 4];
__device__ float g_qkv[3 * BATCH * NHEAD * NSEQ * HDIM];
__device__ float g_comb[BATCH * NHEAD * NSEQ * HDIM];

// ---------------------------------------------------------------------------
// t = x @ U * alpha.  fused over 3 projections via blockIdx.y.
// ---------------------------------------------------------------------------
__global__ __launch_bounds__(256) void k_xu(const float* __restrict__ X,
                                            P3 Us, P3 als, float* __restrict__ Tb) {
    __shared__ float a_s[64][68];
    __shared__ float b_s[64][68];
    int p = blockIdx.y;
    const float* U = sel(Us, p);
    const float* alpha = sel(als, p);
    float* T = Tb + (size_t)p * MROWS * 64;
    int t = threadIdx.x;
    int m0 = blockIdx.x * 64;
    int tq = t & 15, tn = t >> 4;
    u64 acc2[4][2] = {};
    for (int k0 = 0; k0 < 1024; k0 += 64) {
#pragma unroll
        for (int rep = 0; rep < 4; rep++) {
            int fidx = t + rep * 256;
            int m = fidx >> 4, kq = fidx & 15;
            float4 v = *(const float4*)&X[(size_t)(m0 + m) * 1024 + k0 + kq * 4];
            a_s[kq * 4 + 0][m] = v.x; a_s[kq * 4 + 1][m] = v.y;
            a_s[kq * 4 + 2][m] = v.z; a_s[kq * 4 + 3][m] = v.w;
        }
#pragma unroll
        for (int rep = 0; rep < 4; rep++) {
            int fidx = t + rep * 256;
            int kk = fidx >> 4, nq = fidx & 15;
            *(float4*)&b_s[kk][nq * 4] = *(const float4*)&U[(size_t)(k0 + kk) * 64 + nq * 4];
        }
        __syncthreads();
#pragma unroll
        for (int kk = 0; kk < 64; kk++) {
            float4 av = *(const float4*)&a_s[kk][tq * 4];
            ulonglong2 bp = *(const ulonglong2*)&b_s[kk][tn * 4];
            u64 d0 = DUP(av.x), d1 = DUP(av.y), d2 = DUP(av.z), d3 = DUP(av.w);
            FMA2(acc2[0][0], d0, bp.x); FMA2(acc2[0][1], d0, bp.y);
            FMA2(acc2[1][0], d1, bp.x); FMA2(acc2[1][1], d1, bp.y);
            FMA2(acc2[2][0], d2, bp.x); FMA2(acc2[2][1], d2, bp.y);
            FMA2(acc2[3][0], d3, bp.x); FMA2(acc2[3][1], d3, bp.y);
        }
        __syncthreads();
    }
    float a0 = alpha[tn * 4 + 0], a1 = alpha[tn * 4 + 1];
    float a2 = alpha[tn * 4 + 2], a3 = alpha[tn * 4 + 3];
#pragma unroll
    for (int i = 0; i < 4; i++) {
        float2 c0 = UPK(acc2[i][0]), c1 = UPK(acc2[i][1]);
        float4 o = make_float4(c0.x * a0, c0.y * a1, c1.x * a2, c1.y * a3);
        *(float4*)&T[(size_t)(m0 + tq * 4 + i) * 64 + tn * 4] = o;
    }
}

// ---------------------------------------------------------------------------
// l = x @ A, all 3 projections (12 cols) in one pass over x.
// ---------------------------------------------------------------------------
__global__ __launch_bounds__(128) void k_lora(const float* __restrict__ X,
                                              P3 As, float* __restrict__ Lb) {
    int m = blockIdx.x;
    int t = threadIdx.x;
    float p[12] = {};
    const float* A0 = As.a; const float* A1 = As.b; const float* A2 = As.c;
    for (int k = t; k < 1024; k += 128) {
        float xv = X[(size_t)m * 1024 + k];
#pragma unroll
        for (int j = 0; j < 4; j++) {
            p[j]     += xv * A0[k * 4 + j];
            p[4 + j] += xv * A1[k * 4 + j];
            p[8 + j] += xv * A2[k * 4 + j];
        }
    }
    __shared__ float red[12][128];
#pragma unroll
    for (int j = 0; j < 12; j++) red[j][t] = p[j];
    __syncthreads();
    for (int s = 64; s > 0; s >>= 1) {
        if (t < s) {
#pragma unroll
            for (int j = 0; j < 12; j++) red[j][t] += red[j][t + s];
        }
        __syncthreads();
    }
    if (t < 12) {
        int pr = t >> 2, j = t & 3;
        Lb[(size_t)pr * MROWS * 4 + (size_t)m * 4 + j] = red[t][0];
    }
}

// ---------------------------------------------------------------------------
// proj: out = [t | l] @ [V^T ; Blora] + bias -> [B,H,N,HD]. fused z=3.
// ---------------------------------------------------------------------------
__global__ __launch_bounds__(256) void k_proj(const float* __restrict__ Tb,
                                              const float* __restrict__ Lb,
                                              P3 Vs, P3 Bls, P3 bis,
                                              float* __restrict__ QKV) {
    __shared__ float a_s[68][68];
    __shared__ float b_s[68][68];
    int p = blockIdx.z;
    const float* T = Tb + (size_t)p * MROWS * 64;
    const float* L = Lb + (size_t)p * MROWS * 4;
    const float* V = sel(Vs, p);
    const float* Blora = sel(Bls, p);
    const float* bias = sel(bis, p);
    float* O = QKV + (size_t)p * BATCH * NHEAD * NSEQ * HDIM;

    int t = threadIdx.x;
    int m0 = blockIdx.x * 64;
    int n0 = blockIdx.y * 64;
    int tq = t & 15, tn = t >> 4;

#pragma unroll
    for (int rep = 0; rep < 4; rep++) {
        int fidx = t + rep * 256;
        int m = fidx >> 4, kq = fidx & 15;
        float4 v = *(const float4*)&T[(size_t)(m0 + m) * 64 + kq * 4];
        a_s[kq * 4 + 0][m] = v.x; a_s[kq * 4 + 1][m] = v.y;
        a_s[kq * 4 + 2][m] = v.z; a_s[kq * 4 + 3][m] = v.w;
    }
    if (t < 64) {
        float4 lv = *(const float4*)&L[(size_t)(m0 + t) * 4];
        a_s[64][t] = lv.x; a_s[65][t] = lv.y; a_s[66][t] = lv.z; a_s[67][t] = lv.w;
    }
#pragma unroll
    for (int rep = 0; rep < 4; rep++) {
        int fidx = t + rep * 256;
        int n = fidx >> 4, kq = fidx & 15;
        float4 v = *(const float4*)&V[(size_t)(n0 + n) * 64 + kq * 4];
        b_s[kq * 4 + 0][n] = v.x; b_s[kq * 4 + 1][n] = v.y;
        b_s[kq * 4 + 2][n] = v.z; b_s[kq * 4 + 3][n] = v.w;
    }
    {
        int j = t >> 6, n = t & 63;
        b_s[64 + j][n] = Blora[(size_t)j * 1024 + n0 + n];
    }
    __syncthreads();

    u64 acc2[4][2] = {};
#pragma unroll
    for (int kk = 0; kk < 68; kk++) {
        float4 av = *(const float4*)&a_s[kk][tq * 4];
        ulonglong2 bp = *(const ulonglong2*)&b_s[kk][tn * 4];
        u64 d0 = DUP(av.x), d1 = DUP(av.y), d2 = DUP(av.z), d3 = DUP(av.w);
        FMA2(acc2[0][0], d0, bp.x); FMA2(acc2[0][1], d0, bp.y);
        FMA2(acc2[1][0], d1, bp.x); FMA2(acc2[1][1], d1, bp.y);
        FMA2(acc2[2][0], d2, bp.x); FMA2(acc2[2][1], d2, bp.y);
        FMA2(acc2[3][0], d3, bp.x); FMA2(acc2[3][1], d3, bp.y);
    }

    int h = blockIdx.y;
    float b0 = bias[n0 + tn * 4 + 0], b1 = bias[n0 + tn * 4 + 1];
    float b2 = bias[n0 + tn * 4 + 2], b3 = bias[n0 + tn * 4 + 3];
#pragma unroll
    for (int i = 0; i < 4; i++) {
        int m = m0 + tq * 4 + i;
        int bi = m >> 11, ni = m & 2047;
        float2 c0 = UPK(acc2[i][0]), c1 = UPK(acc2[i][1]);
        float4 o = make_float4(c0.x + b0, c0.y + b1, c1.x + b2, c1.y + b3);
        *(float4*)&O[((size_t)(bi * 16 + h) * 2048 + ni) * 64 + tn * 4] = o;
    }
}

// ---------------------------------------------------------------------------
// fused 3-branch flash attention. phases: 0=local, 1=glob, 2=rag.
// ---------------------------------------------------------------------------
__global__ __launch_bounds__(256) void k_attn_all(const float* __restrict__ Q,
                                                  const float* __restrict__ K,
                                                  const float* __restrict__ V,
                                                  const float* __restrict__ MEMV,
                                                  float* __restrict__ O) {
    extern __shared__ float sm[];
    float* q_s = sm;
    float* k_s = sm + 64 * 68;
    float* v_s = sm + 2 * 64 * 68;
    float* p_s = sm + 3 * 64 * 68;
    __shared__ float mrow[64], lrow[64], fac[64];

    int t = threadIdx.x;
    int qt = blockIdx.x;
    int h = blockIdx.y;
    int b = blockIdx.z;
    int tq = t & 15, tz = t >> 4;
    size_t qbase = ((size_t)(b * 16 + h) * 2048 + qt * 64) * 64;

#pragma unroll
    for (int rep = 0; rep < 4; rep++) {
        int fidx = t + rep * 256;
        int q = fidx >> 4, hq = fidx & 15;
        float4 v = *(const float4*)&Q[qbase + (size_t)q * 64 + hq * 4];
        q_s[(hq * 4 + 0) * 68 + q] = v.x; q_s[(hq * 4 + 1) * 68 + q] = v.y;
        q_s[(hq * 4 + 2) * 68 + q] = v.z; q_s[(hq * 4 + 3) * 68 + q] = v.w;
    }
    u64 fin2[4][2] = {};

    for (int ph = 0; ph < 3; ph++) {
        __syncthreads();
        if (t < 64) { mrow[t] = -1e30f; lrow[t] = 0.f; }
        u64 acc2[4][2] = {};
        int c_lo, c_hi;
        if (ph == 0) { c_lo = qt < 2 ? 2 - qt : 0; c_hi = 33 - qt; if (c_hi > 4) c_hi = 4; }
        else if (ph == 1) { c_lo = 0; c_hi = 0; }
        else { c_lo = 0; c_hi = 3; }
        const float* Ksrc = (ph == 2) ? MEMV : K;
        const float* Vsrc = (ph == 2) ? MEMV : V;

        for (int c = c_lo; c <= c_hi; c++) {
#pragma unroll
            for (int rep = 0; rep < 4; rep++) {
                int fidx = t + rep * 256;
                int kk = fidx >> 4, hq = fidx & 15;
                bool valid; size_t rowoff;
                if (ph == 0) {
                    int gk = qt * 64 - 128 + c * 64 + kk;
                    valid = (gk >= 0 && gk < 2048);
                    rowoff = ((size_t)(b * 16 + h) * 2048 + (valid ? gk : 0)) * 64;
                } else if (ph == 1) {
                    valid = kk < 32;
                    rowoff = ((size_t)(b * 16 + h) * 2048 + (valid ? kk * 64 : 0)) * 64;
                } else {
                    valid = true;
                    rowoff = ((size_t)b * 256 + c * 64 + kk) * 64;
                }
                float4 kv = valid ? *(const float4*)&Ksrc[rowoff + hq * 4] : make_float4(0, 0, 0, 0);
                float4 vv = valid ? *(const float4*)&Vsrc[rowoff + hq * 4] : make_float4(0, 0, 0, 0);
                k_s[(hq * 4 + 0) * 68 + kk] = kv.x; k_s[(hq * 4 + 1) * 68 + kk] = kv.y;
                k_s[(hq * 4 + 2) * 68 + kk] = kv.z; k_s[(hq * 4 + 3) * 68 + kk] = kv.w;
                *(float4*)&v_s[kk * 68 + hq * 4] = vv;
            }
            __syncthreads();

            // QK^T
            u64 sc2[4][2] = {};
#pragma unroll
            for (int hd = 0; hd < 64; hd++) {
                float4 qv = *(const float4*)&q_s[hd * 68 + tq * 4];
                ulonglong2 kp = *(const ulonglong2*)&k_s[hd * 68 + tz * 4];
                u64 d0 = DUP(qv.x), d1 = DUP(qv.y), d2 = DUP(qv.z), d3 = DUP(qv.w);
                FMA2(sc2[0][0], d0, kp.x); FMA2(sc2[0][1], d0, kp.y);
                FMA2(sc2[1][0], d1, kp.x); FMA2(sc2[1][1], d1, kp.y);
                FMA2(sc2[2][0], d2, kp.x); FMA2(sc2[2][1], d2, kp.y);
                FMA2(sc2[3][0], d3, kp.x); FMA2(sc2[3][1], d3, kp.y);
            }
#pragma unroll
            for (int i = 0; i < 4; i++) {
                float2 s0 = UPK(sc2[i][0]), s1 = UPK(sc2[i][1]);
                float sv[4] = {s0.x, s0.y, s1.x, s1.y};
                int gq = qt * 64 + tq * 4 + i;
#pragma unroll
                for (int j = 0; j < 4; j++) {
                    int kl = tz * 4 + j;
                    bool ok;
                    if (ph == 0) {
                        int gk = qt * 64 - 128 + c * 64 + kl;
                        int dd = gq - gk; if (dd < 0) dd = -dd;
                        ok = (gk >= 0) && (gk < 2048) && (dd <= WINR);
                    } else if (ph == 1) ok = kl < 32;
                    else ok = true;
                    p_s[kl * 68 + tq * 4 + i] = ok ? sv[j] * ASCALE : -1e30f;
                }
            }
            __syncthreads();

            // parallel online softmax: 64 rows x 4 threads
            {
                int q = t >> 2, part = t & 3;
                float om = mrow[q];
                float mx = om;
#pragma unroll
                for (int j = 0; j < 16; j++)
                    mx = fmaxf(mx, p_s[(part + 4 * j) * 68 + q]);
                mx = fmaxf(mx, __shfl_xor_sync(0xffffffffu, mx, 1));
                mx = fmaxf(mx, __shfl_xor_sync(0xffffffffu, mx, 2));
                float okf = (mx > -1e29f) ? 1.f : 0.f;
                float sum = 0.f;
#pragma unroll
                for (int j = 0; j < 16; j++) {
                    int kk = part + 4 * j;
                    float e = okf * __expf(p_s[kk * 68 + q] - mx);
                    p_s[kk * 68 + q] = e;
                    sum += e;
                }
                sum += __shfl_xor_sync(0xffffffffu, sum, 1);
                sum += __shfl_xor_sync(0xffffffffu, sum, 2);
                if (part == 0) {
                    float f = __expf(om - mx);
                    lrow[q] = lrow[q] * f + sum;
                    mrow[q] = mx;
                    fac[q] = f;
                }
            }
            __syncthreads();

            // rescale + PV
            {
                u64 fd0 = DUP(fac[tq * 4 + 0]), fd1 = DUP(fac[tq * 4 + 1]);
                u64 fd2 = DUP(fac[tq * 4 + 2]), fd3 = DUP(fac[tq * 4 + 3]);
                MUL2(acc2[0][0], fd0); MUL2(acc2[0][1], fd0);
                MUL2(acc2[1][0], fd1); MUL2(acc2[1][1], fd1);
                MUL2(acc2[2][0], fd2); MUL2(acc2[2][1], fd2);
                MUL2(acc2[3][0], fd3); MUL2(acc2[3][1], fd3);
            }
#pragma unroll
            for (int kk = 0; kk < 64; kk++) {
                float4 pv = *(const float4*)&p_s[kk * 68 + tq * 4];
                ulonglong2 vp = *(const ulonglong2*)&v_s[kk * 68 + tz * 4];
                u64 d0 = DUP(pv.x), d1 = DUP(pv.y), d2 = DUP(pv.z), d3 = DUP(pv.w);
                FMA2(acc2[0][0], d0, vp.x); FMA2(acc2[0][1], d0, vp.y);
                FMA2(acc2[1][0], d1, vp.x); FMA2(acc2[1][1], d1, vp.y);
                FMA2(acc2[2][0], d2, vp.x); FMA2(acc2[2][1], d2, vp.y);
                FMA2(acc2[3][0], d3, vp.x); FMA2(acc2[3][1], d3, vp.y);
            }
            __syncthreads();
        }

        // fold normalized branch output into final accumulator
#pragma unroll
        for (int i = 0; i < 4; i++) {
            float l = lrow[tq * 4 + i];
            u64 li = DUP(l > 0.f ? 1.f / l : 0.f);
            FMA2(fin2[i][0], acc2[i][0], li);
            FMA2(fin2[i][1], acc2[i][1], li);
        }
    }

    __syncthreads();
#pragma unroll
    for (int i = 0; i < 4; i++) {
        float2 f0 = UPK(fin2[i][0]), f1 = UPK(fin2[i][1]);
        q_s[(tq * 4 + i) * 68 + tz * 4 + 0] = f0.x;
        q_s[(tq * 4 + i) * 68 + tz * 4 + 1] = f0.y;
        q_s[(tq * 4 + i) * 68 + tz * 4 + 2] = f1.x;
        q_s[(tq * 4 + i) * 68 + tz * 4 + 3] = f1.y;
    }
    __syncthreads();
#pragma unroll
    for (int rep = 0; rep < 4; rep++) {
        int fidx = t + rep * 256;
        int q = fidx >> 4, hq = fidx & 15;
        float4 o;
        o.x = q_s[q * 68 + hq * 4 + 0]; o.y = q_s[q * 68 + hq * 4 + 1];
        o.z = q_s[q * 68 + hq * 4 + 2]; o.w = q_s[q * 68 + hq * 4 + 3];
        *(float4*)&O[qbase + (size_t)q * 64 + hq * 4] = o;
    }
}

// ---------------------------------------------------------------------------
// out = fused @ out_W^T + out_b.  128x128 tile, Kc=16, 8x8 micro, f32x2.
// ---------------------------------------------------------------------------
__global__ __launch_bounds__(256) void k_outproj(const float* __restrict__ C,
                                                 const float* __restrict__ W,
                                                 const float* __restrict__ bias,
                                                 float* __restrict__ out) {
    __shared__ float a_s[16][132];
    __shared__ float b_s[16][132];
    int t = threadIdx.x;
    int m0 = blockIdx.x * 128, n0 = blockIdx.y * 128;
    int tq = t & 15, tn = t >> 4;
    u64 acc2[8][4] = {};
    for (int k0 = 0; k0 < 1024; k0 += 16) {
        int hblk = k0 >> 6;
#pragma unroll
        for (int rep = 0; rep < 2; rep++) {
            int fidx = t + rep * 256;
            int m = fidx >> 2, kq = fidx & 3;
            int mg = m0 + m;
            int bi = mg >> 11, ni = mg & 2047;
            int kg = k0 + kq * 4;
            float4 v = *(const float4*)&C[((size_t)(bi * 16 + hblk) * 2048 + ni) * 64 + (kg & 63)];
            a_s[kq * 4 + 0][m] = v.x; a_s[kq * 4 + 1][m] = v.y;
            a_s[kq * 4 + 2][m] = v.z; a_s[kq * 4 + 3][m] = v.w;
        }
#pragma unroll
        for (int rep = 0; rep < 2; rep++) {
            int fidx = t + rep * 256;
            int n = fidx >> 2, kq = fidx & 3;
            float4 v = *(const float4*)&W[(size_t)(n0 + n) * 1024 + k0 + kq * 4];
            b_s[kq * 4 + 0][n] = v.x; b_s[kq * 4 + 1][n] = v.y;
            b_s[kq * 4 + 2][n] = v.z; b_s[kq * 4 + 3][n] = v.w;
        }
        __syncthreads();
#pragma unroll
        for (int kk = 0; kk < 16; kk++) {
            float4 a0 = *(const float4*)&a_s[kk][tq * 8];
            float4 a1 = *(const float4*)&a_s[kk][tq * 8 + 4];
            ulonglong2 bp0 = *(const ulonglong2*)&b_s[kk][tn * 8];
            ulonglong2 bp1 = *(const ulonglong2*)&b_s[kk][tn * 8 + 4];
            float aa[8] = {a0.x, a0.y, a0.z, a0.w, a1.x, a1.y, a1.z, a1.w};
#pragma unroll
            for (int i = 0; i < 8; i++) {
                u64 d = DUP(aa[i]);
                FMA2(acc2[i][0], d, bp0.x); FMA2(acc2[i][1], d, bp0.y);
                FMA2(acc2[i][2], d, bp1.x); FMA2(acc2[i][3], d, bp1.y);
            }
        }
        __syncthreads();
    }
#pragma unroll
    for (int i = 0; i < 8; i++) {
        int m = m0 + tq * 8 + i;
#pragma unroll
        for (int jq = 0; jq < 2; jq++) {
            float2 c0 = UPK(acc2[i][jq * 2 + 0]);
            float2 c1 = UPK(acc2[i][jq * 2 + 1]);
            float4 o;
            o.x = c0.x + bias[n0 + tn * 8 + jq * 4 + 0];
            o.y = c0.y + bias[n0 + tn * 8 + jq * 4 + 1];
            o.z = c1.x + bias[n0 + tn * 8 + jq * 4 + 2];
            o.w = c1.y + bias[n0 + tn * 8 + jq * 4 + 3];
            *(float4*)&out[(size_t)m * 1024 + n0 + tn * 8 + jq * 4] = o;
        }
    }
}

// ---------------------------------------------------------------------------
__global__ __launch_bounds__(128) void k_heads(const float* __restrict__ C,
                                               const float* __restrict__ tW, const float* __restrict__ tb,
                                               const float* __restrict__ iW, const float* __restrict__ ib,
                                               const float* __restrict__ cW, const float* __restrict__ cb,
                                               float* __restrict__ out) {
    int r = blockIdx.x;
    int b = r >> 11, n = r & 2047;
    __shared__ float last[64];
    int t = threadIdx.x;
    if (t < 64) last[t] = C[((size_t)(b * 16) * 2048 + n) * 64 + t];
    __syncthreads();
    if (t < 2) {
        float s = tb[t];
        for (int k = 0; k < 64; k++) s += last[k] * tW[t * 64 + k];
        out[4194304 + (size_t)r * 2 + t] = s;
    } else if (t < 66) {
        int j = t - 2;
        float s = ib[j];
        for (int k = 0; k < 64; k++) s += last[k] * iW[j * 64 + k];
        out[4202496 + (size_t)r * 64 + j] = s;
    } else if (t < 98) {
        int j = t - 66;
        float s = cb[j];
        for (int k = 0; k < 64; k++) s += last[k] * cW[j * 64 + k];
        out[4464640 + (size_t)r * 32 + j] = s;
    }
}

// ---------------------------------------------------------------------------
extern "C" void kernel_launch(void* const* d_in, const int* in_sizes, int n_in,
                              void* d_out, int out_size) {
    const float* x   = (const float*)d_in[0];
    const float* mem = (const float*)d_in[1];
    P3 Us  = { (const float*)d_in[2],  (const float*)d_in[8],  (const float*)d_in[14] };
    P3 Vs  = { (const float*)d_in[3],  (const float*)d_in[9],  (const float*)d_in[15] };
    P3 als = { (const float*)d_in[4],  (const float*)d_in[10], (const float*)d_in[16] };
    P3 As  = { (const float*)d_in[5],  (const float*)d_in[11], (const float*)d_in[17] };
    P3 Bls = { (const float*)d_in[6],  (const float*)d_in[12], (const float*)d_in[18] };
    P3 bis = { (const float*)d_in[7],  (const float*)d_in[13], (const float*)d_in[19] };
    const float* outW = (const float*)d_in[20];
    const float* outb = (const float*)d_in[21];
    const float* tW = (const float*)d_in[22];
    const float* tb = (const float*)d_in[23];
    const float* iW = (const float*)d_in[24];
    const float* ib = (const float*)d_in[25];
    const float* cW = (const float*)d_in[26];
    const float* cb = (const float*)d_in[27];
    float* out = (float*)d_out;

    void *pT, *pL, *pQKV, *pC;
    cudaGetSymbolAddress(&pT, g_t);
    cudaGetSymbolAddress(&pL, g_l);
    cudaGetSymbolAddress(&pQKV, g_qkv);
    cudaGetSymbolAddress(&pC, g_comb);
    float* Tb = (float*)pT;
    float* Lb = (float*)pL;
    float* QKV = (float*)pQKV;
    float* Cb = (float*)pC;
    const size_t QSZ = (size_t)BATCH * NHEAD * NSEQ * HDIM;

    k_xu<<<dim3(64, 3), 256>>>(x, Us, als, Tb);
    k_lora<<<4096, 128>>>(x, As, Lb);
    k_proj<<<dim3(64, 16, 3), 256>>>(Tb, Lb, Vs, Bls, bis, QKV);

    const int SMEM_ATTN = 4 * 64 * 68 * 4;  // 69632 B
    cudaFuncSetAttribute(k_attn_all, cudaFuncAttributeMaxDynamicSharedMemorySize, SMEM_ATTN);
    k_attn_all<<<dim3(32, 16, 2), 256, SMEM_ATTN>>>(QKV, QKV + QSZ, QKV + 2 * QSZ, mem, Cb);

    k_outproj<<<dim3(32, 8), 256>>>(Cb, outW, outb, out);
    k_heads<<<4096, 128>>>(Cb, tW, tb, iW, ib, cW, cb, out);
}